// round 10
// baseline (speedup 1.0000x reference)
#include <cuda_runtime.h>
#include <cuda_fp16.h>
#include <math.h>
#include <stdint.h>

// ---------------------------------------------------------------------------
// Scratch (static device arrays; no allocation allowed).
// ---------------------------------------------------------------------------
__device__ __half g_x16[32u * 512u * 512u];    // x  as f16           [B][T][D]
__device__ __half g_h16[32u * 512u * 1024u];   // h  as f16           [B][T][MID]
__device__ __half g_w1t[64u * 1024u * 512u];   // w1 f16, transposed  [S][N=MID][K=D]
__device__ __half g_w2t[64u * 512u * 1024u];   // w2 f16, transposed  [S][N=O][K=MID]

// ---------------------------------------------------------------------------
// helpers
// ---------------------------------------------------------------------------
__device__ __forceinline__ uint32_t smem_u32(const void* p) {
    uint32_t a;
    asm("{ .reg .u64 t; cvta.to.shared.u64 t, %1; cvt.u32.u64 %0, t; }"
        : "=r"(a) : "l"(p));
    return a;
}

__device__ __forceinline__ void cp_async16(uint32_t saddr, const void* gptr) {
    asm volatile("cp.async.cg.shared.global [%0], [%1], 16;"
                 :: "r"(saddr), "l"(gptr) : "memory");
}
__device__ __forceinline__ void cp_commit() {
    asm volatile("cp.async.commit_group;" ::: "memory");
}
template <int N>
__device__ __forceinline__ void cp_wait() {
    asm volatile("cp.async.wait_group %0;" :: "n"(N) : "memory");
}

__device__ __forceinline__ void ldsm_x4(uint32_t r[4], uint32_t addr) {
    asm volatile("ldmatrix.sync.aligned.m8n8.x4.shared.b16 {%0,%1,%2,%3}, [%4];"
                 : "=r"(r[0]), "=r"(r[1]), "=r"(r[2]), "=r"(r[3])
                 : "r"(addr));
}

__device__ __forceinline__ void mma_f16(float c[4], const uint32_t a[4],
                                        uint32_t b0, uint32_t b1) {
    asm volatile(
        "mma.sync.aligned.m16n8k16.row.col.f32.f16.f16.f32 "
        "{%0,%1,%2,%3}, {%4,%5,%6,%7}, {%8,%9}, {%0,%1,%2,%3};"
        : "+f"(c[0]), "+f"(c[1]), "+f"(c[2]), "+f"(c[3])
        : "r"(a[0]), "r"(a[1]), "r"(a[2]), "r"(a[3]), "r"(b0), "r"(b1));
}

// sid dtype sniff (int32 vs int64), proven in rounds 4-9.
__device__ __forceinline__ int load_sid(const int* __restrict__ raw, int b) {
    bool is64 = true;
    #pragma unroll
    for (int i = 0; i < 16; i++)
        if (raw[2 * i + 1] != 0) { is64 = false; break; }
    int s = is64 ? raw[2 * b] : raw[b];
    if (s < 0) s = 0;
    if (s > 63) s = 63;
    return s;
}

// ---------------------------------------------------------------------------
// Conversion kernels
// ---------------------------------------------------------------------------
__global__ void convert_x_kernel(const float4* __restrict__ in,
                                 uint2* __restrict__ out, int n4) {
    for (int i = blockIdx.x * blockDim.x + threadIdx.x; i < n4;
         i += gridDim.x * blockDim.x) {
        float4 v = in[i];
        __half2 lo = __floats2half2_rn(v.x, v.y);
        __half2 hi = __floats2half2_rn(v.z, v.w);
        uint2 u;
        u.x = *reinterpret_cast<uint32_t*>(&lo);
        u.y = *reinterpret_cast<uint32_t*>(&hi);
        out[i] = u;
    }
}

// w [S][K][N] f32 -> wt [S][N][K] f16, used subjects only. 32x32 smem transpose.
__global__ void convert_w_t_kernel(const float* __restrict__ w,
                                   __half* __restrict__ wt,
                                   const int* __restrict__ sid_raw,
                                   int K, int N) {
    const int s = blockIdx.z;
    {
        bool is64 = true;
        #pragma unroll
        for (int i = 0; i < 16; i++)
            if (sid_raw[2 * i + 1] != 0) { is64 = false; break; }
        bool used = false;
        #pragma unroll
        for (int b = 0; b < 32; b++) {
            int v = is64 ? sid_raw[2 * b] : sid_raw[b];
            if (v == s) used = true;
        }
        if (!used) return;
    }
    __shared__ float tile[32][33];
    const int k0 = blockIdx.y * 32, n0 = blockIdx.x * 32;
    const int tx = threadIdx.x, ty = threadIdx.y;
    const float* wp = w + (size_t)s * K * N;
    __half* wtp = wt + (size_t)s * N * K;
    #pragma unroll
    for (int i = ty; i < 32; i += 8)
        tile[i][tx] = wp[(size_t)(k0 + i) * N + n0 + tx];
    __syncthreads();
    #pragma unroll
    for (int i = ty; i < 32; i += 8)
        wtp[(size_t)(n0 + i) * K + k0 + tx] = __float2half_rn(tile[tx][i]);
}

// ---------------------------------------------------------------------------
// fp16 mma.sync GEMM. BK=32, 3-stage cp.async pipeline, ldmatrix fragments,
// manual LDSM/HMMA interleave.
//   C[b] = act( A[b] @ Wt[sid[b]]^T ) (+ bias[sid[b]])
//   A:  [B, M, K] f16 row-major (K contiguous)
//   Wt: [S, N, K] f16 row-major (K contiguous)
//   CTA tile 128x128, 256 threads (8 warps 4(m)x2(n), warp 32x64).
//   SMEM rows: 32 f16 = 64B data + 16B pad = 80B stride.
//   LDSM banks per 8-row phase: 20*r mod 32 = {0,20,8,28,16,4,24,12} -> all 32.
// ---------------------------------------------------------------------------
#define NSTAGE 3
static constexpr int ROW_B = 80;                  // smem row stride (bytes)
static constexpr int HALF_STG = 128 * ROW_B;      // 10240 B (A or B half)
static constexpr int STG_B = 2 * HALF_STG;        // 20480 B per stage
static constexpr int SMEM_DYN = NSTAGE * STG_B;   // 61440 B

template <bool DO_GELU, bool DO_BIAS, bool STORE_HALF>
__global__ __launch_bounds__(256, 2)
void subject_hgemm(const __half* __restrict__ A_base,
                   const __half* __restrict__ Wt_base,
                   const int* __restrict__ sid_raw,
                   const float* __restrict__ bias_base,
                   void* __restrict__ C_base,
                   int M, int N, int K)
{
    const int b = blockIdx.z;
    const int s = load_sid(sid_raw, b);
    const __half* A = A_base + (size_t)b * M * K;
    const __half* Wt = Wt_base + (size_t)s * N * K;
    const int m0 = blockIdx.y * 128;
    const int n0 = blockIdx.x * 128;

    extern __shared__ char dsm[];
    const uint32_t smem0 = smem_u32(dsm);

    const int tid = threadIdx.x;
    const int wid = tid >> 5;
    const int lane = tid & 31;
    const int wm = wid >> 1;   // 0..3 -> 32-row slab
    const int wn = wid & 1;    // 0..1 -> 64-col slab
    const int g = lane >> 2;   // 0..7
    const int t4 = lane & 3;   // 0..3

    // cp.async: thread -> row tid>>1, 32B-half tid&1 (two 16B cps per half).
    const int cR = tid >> 1, cH = tid & 1;
    const __half* Ag = A + (size_t)(m0 + cR) * K + cH * 16;
    const __half* Bg = Wt + (size_t)(n0 + cR) * K + cH * 16;
    const uint32_t cpOffA = (uint32_t)(cR * ROW_B + cH * 32);
    const uint32_t cpOffB = HALF_STG + cpOffA;

    // ldmatrix lane base addresses (kk=0, stage 0):
    const uint32_t aAddr0 = smem0
        + (uint32_t)((wm * 32 + (lane & 15)) * ROW_B + (lane >> 4) * 16);
    const uint32_t bAddr0 = smem0 + HALF_STG
        + (uint32_t)((wn * 64 + (lane & 7) + ((lane >> 4) << 3)) * ROW_B
                     + ((lane >> 3) & 1) * 16);

    const int NC = K / 32;

    auto issue_stage = [&](int c) {
        const uint32_t base = smem0 + (uint32_t)((c % NSTAGE) * STG_B);
        const int k0 = c * 32;
        cp_async16(base + cpOffA,      Ag + k0);
        cp_async16(base + cpOffA + 16, Ag + k0 + 8);
        cp_async16(base + cpOffB,      Bg + k0);
        cp_async16(base + cpOffB + 16, Bg + k0 + 8);
    };

    float acc[2][8][4];
    #pragma unroll
    for (int i = 0; i < 2; i++)
        #pragma unroll
        for (int j = 0; j < 8; j++)
            #pragma unroll
            for (int q = 0; q < 4; q++)
                acc[i][j][q] = 0.0f;

    #pragma unroll
    for (int c = 0; c < NSTAGE - 1; c++) {
        issue_stage(c);
        cp_commit();
    }

    #pragma unroll 1
    for (int c = 0; c < NC; c++) {
        cp_wait<NSTAGE - 2>();
        __syncthreads();

        if (c + NSTAGE - 1 < NC) issue_stage(c + NSTAGE - 1);
        cp_commit();

        const uint32_t soff = (uint32_t)((c % NSTAGE) * STG_B);
        const uint32_t aA = aAddr0 + soff;
        const uint32_t bA = bAddr0 + soff;

        // A fragments for both k-halves (kk byte offset: kk*2 -> 0 / 32).
        uint32_t af[2][2][4];  // [kk][fm][4]
        ldsm_x4(af[0][0], aA);
        ldsm_x4(af[0][1], aA + 16 * ROW_B);
        ldsm_x4(af[1][0], aA + 32);
        ldsm_x4(af[1][1], aA + 16 * ROW_B + 32);

        // B fragments, kk=0.
        uint32_t bf[4][4];
        #pragma unroll
        for (int j = 0; j < 4; j++)
            ldsm_x4(bf[j], bA + (uint32_t)(j * 16 * ROW_B));

        // kk=0 MMAs; after consuming bf[j], immediately reload it with kk=16.
        #pragma unroll
        for (int j = 0; j < 4; j++) {
            mma_f16(acc[0][2 * j + 0], af[0][0], bf[j][0], bf[j][1]);
            mma_f16(acc[0][2 * j + 1], af[0][0], bf[j][2], bf[j][3]);
            mma_f16(acc[1][2 * j + 0], af[0][1], bf[j][0], bf[j][1]);
            mma_f16(acc[1][2 * j + 1], af[0][1], bf[j][2], bf[j][3]);
            ldsm_x4(bf[j], bA + (uint32_t)(j * 16 * ROW_B) + 32);
        }
        // kk=16 MMAs.
        #pragma unroll
        for (int j = 0; j < 4; j++) {
            mma_f16(acc[0][2 * j + 0], af[1][0], bf[j][0], bf[j][1]);
            mma_f16(acc[0][2 * j + 1], af[1][0], bf[j][2], bf[j][3]);
            mma_f16(acc[1][2 * j + 0], af[1][1], bf[j][0], bf[j][1]);
            mma_f16(acc[1][2 * j + 1], af[1][1], bf[j][2], bf[j][3]);
        }
    }

    // ---- epilogue ----
    const float* brow = DO_BIAS ? (bias_base + (size_t)s * N + n0) : nullptr;

    #pragma unroll
    for (int fm = 0; fm < 2; fm++) {
        const int r0 = m0 + wm * 32 + fm * 16 + g;
        #pragma unroll
        for (int fn = 0; fn < 8; fn++) {
            const int col = wn * 64 + fn * 8 + t4 * 2;
            #pragma unroll
            for (int h2 = 0; h2 < 2; h2++) {
                const int row = r0 + 8 * h2;
                float v0 = acc[fm][fn][2 * h2 + 0];
                float v1 = acc[fm][fn][2 * h2 + 1];
                if (DO_BIAS) {
                    v0 += brow[col];
                    v1 += brow[col + 1];
                }
                if (DO_GELU) {
                    v0 = 0.5f * v0 * (1.0f + erff(v0 * 0.70710678118654752f));
                    v1 = 0.5f * v1 * (1.0f + erff(v1 * 0.70710678118654752f));
                }
                if (STORE_HALF) {
                    __half2 hv = __floats2half2_rn(v0, v1);
                    *reinterpret_cast<__half2*>(
                        (__half*)C_base + (size_t)b * M * N +
                        (size_t)row * N + n0 + col) = hv;
                } else {
                    *reinterpret_cast<float2*>(
                        (float*)C_base + (size_t)b * M * N +
                        (size_t)row * N + n0 + col) = make_float2(v0, v1);
                }
            }
        }
    }
}

// ---------------------------------------------------------------------------
extern "C" void kernel_launch(void* const* d_in, const int* in_sizes, int n_in,
                              void* d_out, int out_size) {
    const float* x = (const float*)d_in[0];     // [32, 512, 512]
    const int* sid_raw = (const int*)d_in[1];   // [32] int32 or int64 (sniffed)
    const float* w1 = (const float*)d_in[2];    // [64, 512, 1024]
    const float* w2 = (const float*)d_in[3];    // [64, 1024, 512]
    const float* bias = (const float*)d_in[4];  // [64, 512]
    float* out = (float*)d_out;                 // [32, 512, 512]

    const int B = 32, T = 512, D = 512, MID = 1024, O = 512;
    (void)in_sizes; (void)n_in; (void)out_size;

    __half *x16, *h16, *w1t, *w2t;
    cudaGetSymbolAddress((void**)&x16, g_x16);
    cudaGetSymbolAddress((void**)&h16, g_h16);
    cudaGetSymbolAddress((void**)&w1t, g_w1t);
    cudaGetSymbolAddress((void**)&w2t, g_w2t);

    (void)cudaFuncSetAttribute(
        (const void*)subject_hgemm<true, false, true>,
        cudaFuncAttributeMaxDynamicSharedMemorySize, SMEM_DYN);
    (void)cudaFuncSetAttribute(
        (const void*)subject_hgemm<false, true, false>,
        cudaFuncAttributeMaxDynamicSharedMemorySize, SMEM_DYN);

    // 1) x -> f16
    {
        const int n4 = (B * T * D) / 4;
        convert_x_kernel<<<4096, 256>>>((const float4*)x, (uint2*)x16, n4);
    }
    // 2) w1, w2 -> f16 transposed [S][N][K], used subjects only
    {
        dim3 tb(32, 8);
        convert_w_t_kernel<<<dim3(MID / 32, D / 32, 64), tb>>>(w1, w1t, sid_raw, D, MID);
        convert_w_t_kernel<<<dim3(O / 32, MID / 32, 64), tb>>>(w2, w2t, sid_raw, MID, O);
    }
    // 3) GEMM1 + GELU -> h16:  (M=512, N=1024, K=512)
    {
        dim3 grid(MID / 128, T / 128, B);
        subject_hgemm<true, false, true><<<grid, 256, SMEM_DYN>>>(
            x16, w1t, sid_raw, nullptr, (void*)h16, T, MID, D);
    }
    // 4) GEMM2 + bias -> out f32:  (M=512, N=512, K=1024)
    {
        dim3 grid(O / 128, T / 128, B);
        subject_hgemm<false, true, false><<<grid, 256, SMEM_DYN>>>(
            h16, w2t, sid_raw, bias, (void*)out, T, O, MID);
    }
}

// round 11
// speedup vs baseline: 1.4388x; 1.4388x over previous
#include <cuda_runtime.h>
#include <cuda_fp16.h>
#include <math.h>
#include <stdint.h>

// ---------------------------------------------------------------------------
// Scratch (static device arrays; no allocation allowed).
// ---------------------------------------------------------------------------
__device__ __half g_x16[32u * 512u * 512u];    // x  as f16   [B][T][D]
__device__ __half g_h16[32u * 512u * 1024u];   // h  as f16   [B][T][MID]
__device__ __half g_w1h[64u * 512u * 1024u];   // w1 f16      [S][K=D][N=MID]
__device__ __half g_w2h[64u * 1024u * 512u];   // w2 f16      [S][K=MID][N=O]

// ---------------------------------------------------------------------------
// helpers
// ---------------------------------------------------------------------------
__device__ __forceinline__ uint32_t smem_u32(const void* p) {
    uint32_t a;
    asm("{ .reg .u64 t; cvta.to.shared.u64 t, %1; cvt.u32.u64 %0, t; }"
        : "=r"(a) : "l"(p));
    return a;
}

__device__ __forceinline__ void cp_async16(uint32_t saddr, const void* gptr) {
    asm volatile("cp.async.cg.shared.global [%0], [%1], 16;"
                 :: "r"(saddr), "l"(gptr) : "memory");
}
__device__ __forceinline__ void cp_commit() {
    asm volatile("cp.async.commit_group;" ::: "memory");
}
template <int N>
__device__ __forceinline__ void cp_wait() {
    asm volatile("cp.async.wait_group %0;" :: "n"(N) : "memory");
}

__device__ __forceinline__ void ldsm_x4(uint32_t r[4], uint32_t addr) {
    asm volatile("ldmatrix.sync.aligned.m8n8.x4.shared.b16 {%0,%1,%2,%3}, [%4];"
                 : "=r"(r[0]), "=r"(r[1]), "=r"(r[2]), "=r"(r[3])
                 : "r"(addr));
}
__device__ __forceinline__ void ldsm_x4_t(uint32_t r[4], uint32_t addr) {
    asm volatile("ldmatrix.sync.aligned.m8n8.x4.trans.shared.b16 {%0,%1,%2,%3}, [%4];"
                 : "=r"(r[0]), "=r"(r[1]), "=r"(r[2]), "=r"(r[3])
                 : "r"(addr));
}

__device__ __forceinline__ void mma_f16(float c[4], const uint32_t a[4],
                                        uint32_t b0, uint32_t b1) {
    asm volatile(
        "mma.sync.aligned.m16n8k16.row.col.f32.f16.f16.f32 "
        "{%0,%1,%2,%3}, {%4,%5,%6,%7}, {%8,%9}, {%0,%1,%2,%3};"
        : "+f"(c[0]), "+f"(c[1]), "+f"(c[2]), "+f"(c[3])
        : "r"(a[0]), "r"(a[1]), "r"(a[2]), "r"(a[3]), "r"(b0), "r"(b1));
}

// sid dtype sniff (int32 vs int64), proven in rounds 4-10.
__device__ __forceinline__ int load_sid(const int* __restrict__ raw, int b) {
    bool is64 = true;
    #pragma unroll
    for (int i = 0; i < 16; i++)
        if (raw[2 * i + 1] != 0) { is64 = false; break; }
    int s = is64 ? raw[2 * b] : raw[b];
    if (s < 0) s = 0;
    if (s > 63) s = 63;
    return s;
}

__device__ __forceinline__ bool subject_used(const int* __restrict__ raw, int s) {
    bool is64 = true;
    #pragma unroll
    for (int i = 0; i < 16; i++)
        if (raw[2 * i + 1] != 0) { is64 = false; break; }
    #pragma unroll
    for (int b = 0; b < 32; b++) {
        int v = is64 ? raw[2 * b] : raw[b];
        if (v == s) return true;
    }
    return false;
}

// ---------------------------------------------------------------------------
// Conversion kernels (pure streaming; no transpose needed anymore)
// ---------------------------------------------------------------------------
__global__ void convert_x_kernel(const float4* __restrict__ in,
                                 uint2* __restrict__ out, int n4) {
    for (int i = blockIdx.x * blockDim.x + threadIdx.x; i < n4;
         i += gridDim.x * blockDim.x) {
        float4 v = in[i];
        __half2 lo = __floats2half2_rn(v.x, v.y);
        __half2 hi = __floats2half2_rn(v.z, v.w);
        uint2 u;
        u.x = *reinterpret_cast<uint32_t*>(&lo);
        u.y = *reinterpret_cast<uint32_t*>(&hi);
        out[i] = u;
    }
}

// w [S][K][N] f32 -> f16 same layout, used subjects only.
__global__ void convert_w_kernel(const float4* __restrict__ in,
                                 uint2* __restrict__ out,
                                 const int* __restrict__ sid_raw,
                                 int elems4_per_subject) {
    const int s = blockIdx.z;
    if (!subject_used(sid_raw, s)) return;
    const float4* ip = in + (size_t)s * elems4_per_subject;
    uint2* op = out + (size_t)s * elems4_per_subject;
    for (int i = blockIdx.x * blockDim.x + threadIdx.x; i < elems4_per_subject;
         i += gridDim.x * blockDim.x) {
        float4 v = ip[i];
        __half2 lo = __floats2half2_rn(v.x, v.y);
        __half2 hi = __floats2half2_rn(v.z, v.w);
        uint2 u;
        u.x = *reinterpret_cast<uint32_t*>(&lo);
        u.y = *reinterpret_cast<uint32_t*>(&hi);
        op[i] = u;
    }
}

// ---------------------------------------------------------------------------
// fp16 mma.sync GEMM. BK=16, 6-stage cp.async pipeline.
//   C[b] = act( A[b] @ W[sid[b]] ) (+ bias[sid[b]])
//   A: [B, M, K] f16 row-major (K contiguous)  -> ldmatrix (non-trans)
//   W: [S, K, N] f16 row-major (N contiguous)  -> ldmatrix.trans
//   CTA tile 128x128, 256 threads (8 warps 4(m)x2(n), warp 32x64).
//   A smem rows: 16 f16 = 32B + 16B pad = 48B stride (conflict-free phases).
//   B smem rows: 128 f16 = 256B + 16B pad = 272B stride (272/4 % 32 == 4 ->
//   8-row LDSM phases cover all 32 banks).
// ---------------------------------------------------------------------------
#define NSTAGE 6
static constexpr int A_ROW_B = 48;
static constexpr int B_ROW_B = 272;
static constexpr int A_STG = 128 * A_ROW_B;       // 6144 B
static constexpr int B_STG = 16 * B_ROW_B;        // 4352 B
static constexpr int STG_B = A_STG + B_STG;       // 10496 B
static constexpr int SMEM_DYN = NSTAGE * STG_B;   // 62976 B

template <bool DO_GELU, bool DO_BIAS, bool STORE_HALF>
__global__ __launch_bounds__(256, 2)
void subject_hgemm(const __half* __restrict__ A_base,
                   const __half* __restrict__ W_base,
                   const int* __restrict__ sid_raw,
                   const float* __restrict__ bias_base,
                   void* __restrict__ C_base,
                   int M, int N, int K)
{
    const int b = blockIdx.z;
    const int s = load_sid(sid_raw, b);
    const __half* A = A_base + (size_t)b * M * K;
    const __half* W = W_base + (size_t)s * K * N;
    const int m0 = blockIdx.y * 128;
    const int n0 = blockIdx.x * 128;

    extern __shared__ char dsm[];
    const uint32_t smem0 = smem_u32(dsm);

    const int tid = threadIdx.x;
    const int wid = tid >> 5;
    const int lane = tid & 31;
    const int wm = wid >> 1;   // 0..3 -> 32-row slab
    const int wn = wid & 1;    // 0..1 -> 64-col slab
    const int g = lane >> 2;   // 0..7
    const int t4 = lane & 3;   // 0..3

    // cp.async A: thread -> m-row tid>>1, 16B half tid&1.
    const int aR = tid >> 1, aH = tid & 1;
    const __half* Ag = A + (size_t)(m0 + aR) * K + aH * 8;
    const uint32_t cpOffA = (uint32_t)(aR * A_ROW_B + aH * 16);
    // cp.async B: thread -> k-row tid>>4, 16B segment tid&15 (coalesced in n).
    const int bR = tid >> 4, bS = tid & 15;
    const __half* Bg = W + (size_t)bR * N + n0 + bS * 8;
    const uint32_t cpOffB = (uint32_t)(A_STG + bR * B_ROW_B + bS * 16);

    // ldmatrix lane addresses.
    const uint32_t aAddr0 = smem0
        + (uint32_t)((wm * 32 + (lane & 15)) * A_ROW_B + (lane >> 4) * 16);
    //  B trans .x4: matrices (k-half kh, n-half nh):
    //   lanes 0-7: kh=0,nh=0; 8-15: kh=1,nh=0; 16-23: kh=0,nh=1; 24-31: kh=1,nh=1.
    const int bRow = ((lane >> 3) & 1) * 8 + (lane & 7);     // k row within 16
    const int bNh = (lane >> 4) * 8;                          // n sub-offset
    const uint32_t bAddr0 = smem0
        + (uint32_t)(A_STG + bRow * B_ROW_B + (wn * 64 + bNh) * 2);

    const int NC = K / 16;

    auto issue_stage = [&](int c) {
        const uint32_t base = smem0 + (uint32_t)((c % NSTAGE) * STG_B);
        const int k0 = c * 16;
        cp_async16(base + cpOffA, Ag + k0);
        cp_async16(base + cpOffB, Bg + (size_t)k0 * N);
    };

    float acc[2][8][4];
    #pragma unroll
    for (int i = 0; i < 2; i++)
        #pragma unroll
        for (int j = 0; j < 8; j++)
            #pragma unroll
            for (int q = 0; q < 4; q++)
                acc[i][j][q] = 0.0f;

    #pragma unroll
    for (int c = 0; c < NSTAGE - 1; c++) {
        issue_stage(c);
        cp_commit();
    }

    #pragma unroll 1
    for (int c = 0; c < NC; c++) {
        cp_wait<NSTAGE - 2>();
        __syncthreads();

        if (c + NSTAGE - 1 < NC) issue_stage(c + NSTAGE - 1);
        cp_commit();

        const uint32_t soff = (uint32_t)((c % NSTAGE) * STG_B);

        uint32_t af[2][4];
        ldsm_x4(af[0], aAddr0 + soff);
        ldsm_x4(af[1], aAddr0 + soff + 16 * A_ROW_B);

        // bf[j]: regs 0,1 = n-group 2j (k0-7, k8-15); regs 2,3 = n-group 2j+1.
        uint32_t bf[4][4];
        #pragma unroll
        for (int j = 0; j < 4; j++)
            ldsm_x4_t(bf[j], bAddr0 + soff + (uint32_t)(j * 32));  // j*16 cols

        #pragma unroll
        for (int fm = 0; fm < 2; fm++)
            #pragma unroll
            for (int j = 0; j < 4; j++) {
                mma_f16(acc[fm][2 * j + 0], af[fm], bf[j][0], bf[j][1]);
                mma_f16(acc[fm][2 * j + 1], af[fm], bf[j][2], bf[j][3]);
            }
    }

    // ---- epilogue ----
    const float* brow = DO_BIAS ? (bias_base + (size_t)s * N + n0) : nullptr;

    #pragma unroll
    for (int fm = 0; fm < 2; fm++) {
        const int r0 = m0 + wm * 32 + fm * 16 + g;
        #pragma unroll
        for (int fn = 0; fn < 8; fn++) {
            const int col = wn * 64 + fn * 8 + t4 * 2;
            #pragma unroll
            for (int h2 = 0; h2 < 2; h2++) {
                const int row = r0 + 8 * h2;
                float v0 = acc[fm][fn][2 * h2 + 0];
                float v1 = acc[fm][fn][2 * h2 + 1];
                if (DO_BIAS) {
                    v0 += brow[col];
                    v1 += brow[col + 1];
                }
                if (DO_GELU) {
                    v0 = 0.5f * v0 * (1.0f + erff(v0 * 0.70710678118654752f));
                    v1 = 0.5f * v1 * (1.0f + erff(v1 * 0.70710678118654752f));
                }
                if (STORE_HALF) {
                    __half2 hv = __floats2half2_rn(v0, v1);
                    *reinterpret_cast<__half2*>(
                        (__half*)C_base + (size_t)b * M * N +
                        (size_t)row * N + n0 + col) = hv;
                } else {
                    *reinterpret_cast<float2*>(
                        (float*)C_base + (size_t)b * M * N +
                        (size_t)row * N + n0 + col) = make_float2(v0, v1);
                }
            }
        }
    }
}

// ---------------------------------------------------------------------------
extern "C" void kernel_launch(void* const* d_in, const int* in_sizes, int n_in,
                              void* d_out, int out_size) {
    const float* x = (const float*)d_in[0];     // [32, 512, 512]
    const int* sid_raw = (const int*)d_in[1];   // [32] int32 or int64 (sniffed)
    const float* w1 = (const float*)d_in[2];    // [64, 512, 1024]
    const float* w2 = (const float*)d_in[3];    // [64, 1024, 512]
    const float* bias = (const float*)d_in[4];  // [64, 512]
    float* out = (float*)d_out;                 // [32, 512, 512]

    const int B = 32, T = 512, D = 512, MID = 1024, O = 512;
    (void)in_sizes; (void)n_in; (void)out_size;

    __half *x16, *h16, *w1h, *w2h;
    cudaGetSymbolAddress((void**)&x16, g_x16);
    cudaGetSymbolAddress((void**)&h16, g_h16);
    cudaGetSymbolAddress((void**)&w1h, g_w1h);
    cudaGetSymbolAddress((void**)&w2h, g_w2h);

    (void)cudaFuncSetAttribute(
        (const void*)subject_hgemm<true, false, true>,
        cudaFuncAttributeMaxDynamicSharedMemorySize, SMEM_DYN);
    (void)cudaFuncSetAttribute(
        (const void*)subject_hgemm<false, true, false>,
        cudaFuncAttributeMaxDynamicSharedMemorySize, SMEM_DYN);

    // 1) x -> f16
    {
        const int n4 = (B * T * D) / 4;
        convert_x_kernel<<<2048, 256>>>((const float4*)x, (uint2*)x16, n4);
    }
    // 2) w1, w2 -> f16 same layout, used subjects only
    {
        const int e4 = (D * MID) / 4;  // 131072 per subject (same for w2)
        convert_w_kernel<<<dim3(128, 1, 64), 256>>>(
            (const float4*)w1, (uint2*)w1h, sid_raw, e4);
        convert_w_kernel<<<dim3(128, 1, 64), 256>>>(
            (const float4*)w2, (uint2*)w2h, sid_raw, e4);
    }
    // 3) GEMM1 + GELU -> h16:  (M=512, N=1024, K=512)
    {
        dim3 grid(MID / 128, T / 128, B);
        subject_hgemm<true, false, true><<<grid, 256, SMEM_DYN>>>(
            x16, w1h, sid_raw, nullptr, (void*)h16, T, MID, D);
    }
    // 4) GEMM2 + bias -> out f32:  (M=512, N=512, K=1024)
    {
        dim3 grid(O / 128, T / 128, B);
        subject_hgemm<false, true, false><<<grid, 256, SMEM_DYN>>>(
            h16, w2h, sid_raw, bias, (void*)out, T, O, MID);
    }
}